// round 5
// baseline (speedup 1.0000x reference)
#include <cuda_runtime.h>
#include <cstdint>

#define T_STEPS 2048
#define BATCH 16
#define DIM 1024
#define NCTA 128
#define STEP_ELEMS (BATCH * DIM)                  // 16384
#define OUTS_ELEMS ((size_t)T_STEPS * STEP_ELEMS) // 33554432

typedef unsigned long long ull;

// Monotonic grid-barrier counter. Reset by init_kernel every launch/replay.
__device__ unsigned int g_count;
// Transposed h scratch, ping-pong: g_hscr[p][d*16 + b] = h[b][d].
__device__ __align__(16) float g_hscr[2][STEP_ELEMS];

__device__ __forceinline__ float my_tanh(float x) {
    float ax = fabsf(x);
    float e  = __expf(2.0f * ax);
    float r  = 1.0f - 2.0f / (e + 1.0f);
    return copysignf(r, x);
}
__device__ __forceinline__ float my_sigmoid(float x) {
    return 1.0f / (1.0f + __expf(-x));
}

__device__ __forceinline__ void cp_async16(uint32_t smem_addr, const void* gptr) {
    asm volatile("cp.async.cg.shared.global [%0], [%1], 16;\n"
                 :: "r"(smem_addr), "l"(gptr) : "memory");
}
__device__ __forceinline__ void cp_commit() {
    asm volatile("cp.async.commit_group;\n" ::: "memory");
}
#define CP_WAIT(n) asm volatile("cp.async.wait_group %0;\n" :: "n"(n) : "memory")

__device__ __forceinline__ void bar_arrive_release() {
    unsigned* p = &g_count;
    asm volatile("red.add.release.gpu.u32 [%0], %1;" :: "l"(p), "r"(1u) : "memory");
}
__device__ __forceinline__ unsigned bar_ld_acquire() {
    unsigned v;
    unsigned* p = &g_count;
    asm volatile("ld.acquire.gpu.u32 %0, [%1];" : "=r"(v) : "l"(p) : "memory");
    return v;
}

// Packed f32x2 FMA: {d.lo,d.hi} = {a.lo*b.lo+c.lo, a.hi*b.hi+c.hi}
__device__ __forceinline__ void ffma2(ull& acc, ull a, ull b) {
    asm("fma.rn.f32x2 %0, %1, %2, %0;" : "+l"(acc) : "l"(a), "l"(b));
}
__device__ __forceinline__ ull pack2(float x) {
    ull r;
    asm("mov.b64 %0, {%1, %1};" : "=l"(r) : "f"(x));
    return r;
}
__device__ __forceinline__ void lds128(ull& lo, ull& hi, uint32_t addr) {
    asm volatile("ld.shared.v2.u64 {%0, %1}, [%2];" : "=l"(lo), "=l"(hi) : "r"(addr));
}
__device__ __forceinline__ void sts128(uint32_t addr, ull lo, ull hi) {
    asm volatile("st.shared.v2.u64 [%0], {%1, %2};" :: "r"(addr), "l"(lo), "l"(hi));
}
__device__ __forceinline__ float lds32(uint32_t addr) {
    float v;
    asm volatile("ld.shared.f32 %0, [%1];" : "=f"(v) : "r"(addr));
    return v;
}

// ---------------------------------------------------------------------------
// Init: h0 -> hbuf slot 0 (canonical) and g_hscr[0] (transposed); reset barrier.
// ---------------------------------------------------------------------------
__global__ void init_kernel(const float* __restrict__ h0, float* __restrict__ hbuf) {
    int i = blockIdx.x * blockDim.x + threadIdx.x;
    if (i < STEP_ELEMS) {
        float v = h0[i];
        hbuf[i] = v;
        int b = i >> 10, d = i & 1023;
        g_hscr[0][d * 16 + b] = v;
    }
    if (i == 0) g_count = 0u;
}

// ---------------------------------------------------------------------------
// GEMM: C[m,n] = sum_k A[m,k]*B[n,k] + bias[n]. (unchanged from R4)
// ---------------------------------------------------------------------------
__global__ void __launch_bounds__(256, 2)
gemm_kernel(const float* __restrict__ A, const float* __restrict__ Bw,
            const float* __restrict__ bias, float* __restrict__ C) {
    __shared__ float As[2][8][128];
    __shared__ float Bs[2][8][128];

    const int tid = threadIdx.x;
    const int m0 = blockIdx.x * 128;
    const int n0 = blockIdx.y * 128;
    const int lr = tid >> 1;
    const int lc = (tid & 1) * 4;
    const int tx = tid & 15;
    const int ty = tid >> 4;

    const float* Ab = A  + (size_t)(m0 + lr) * DIM + lc;
    const float* Bb = Bw + (size_t)(n0 + lr) * DIM + lc;

    float acc[8][8];
#pragma unroll
    for (int i = 0; i < 8; i++)
#pragma unroll
        for (int j = 0; j < 8; j++) acc[i][j] = 0.0f;

    {
        float4 a4 = *(const float4*)Ab;
        float4 b4 = *(const float4*)Bb;
        As[0][lc + 0][lr] = a4.x; As[0][lc + 1][lr] = a4.y;
        As[0][lc + 2][lr] = a4.z; As[0][lc + 3][lr] = a4.w;
        Bs[0][lc + 0][lr] = b4.x; Bs[0][lc + 1][lr] = b4.y;
        Bs[0][lc + 2][lr] = b4.z; Bs[0][lc + 3][lr] = b4.w;
    }
    __syncthreads();

#pragma unroll 1
    for (int kt = 0; kt < 128; kt++) {
        const int cur = kt & 1;
        float4 na, nb;
        if (kt < 127) {
            na = *(const float4*)(Ab + (kt + 1) * 8);
            nb = *(const float4*)(Bb + (kt + 1) * 8);
        }
#pragma unroll
        for (int kk = 0; kk < 8; kk++) {
            float af[8], bf[8];
            *(float4*)&af[0] = *(const float4*)&As[cur][kk][ty * 8];
            *(float4*)&af[4] = *(const float4*)&As[cur][kk][ty * 8 + 4];
            *(float4*)&bf[0] = *(const float4*)&Bs[cur][kk][tx * 8];
            *(float4*)&bf[4] = *(const float4*)&Bs[cur][kk][tx * 8 + 4];
#pragma unroll
            for (int i = 0; i < 8; i++)
#pragma unroll
                for (int j = 0; j < 8; j++)
                    acc[i][j] = fmaf(af[i], bf[j], acc[i][j]);
        }
        if (kt < 127) {
            const int nxt = cur ^ 1;
            As[nxt][lc + 0][lr] = na.x; As[nxt][lc + 1][lr] = na.y;
            As[nxt][lc + 2][lr] = na.z; As[nxt][lc + 3][lr] = na.w;
            Bs[nxt][lc + 0][lr] = nb.x; Bs[nxt][lc + 1][lr] = nb.y;
            Bs[nxt][lc + 2][lr] = nb.z; Bs[nxt][lc + 3][lr] = nb.w;
        }
        __syncthreads();
    }

#pragma unroll
    for (int i = 0; i < 8; i++) {
        size_t row = (size_t)(m0 + ty * 8 + i) * DIM + n0 + tx * 8;
#pragma unroll
        for (int j = 0; j < 8; j++)
            C[row + j] = acc[i][j] + bias[n0 + tx * 8 + j];
    }
}

// ---------------------------------------------------------------------------
// Persistent recurrence. 128 CTAs x 256 threads; CTA owns 8 e-columns.
// h staged TRANSPOSED in smem: logical float idx = k_local*16 + b within each
// of 4 k-groups (16 KB each), with per-256B-block rotation swizzle
// (slot' = (slot + block) & 15) for conflict-free access.
// Thread (e_pair = tid&3, c4 = tid>>2): 2 e-columns, 16 k's (4 per group),
// all 16 batches, via packed fma.rn.f32x2 over batch pairs.
// ---------------------------------------------------------------------------
__global__ void __launch_bounds__(256, 1)
rnn_kernel(const float* __restrict__ Wh, const float* __restrict__ la,
           float* __restrict__ outs, float* __restrict__ hbuf) {
    extern __shared__ float sm[];
    const uint32_t h_u32    = (uint32_t)__cvta_generic_to_shared(sm);
    const uint32_t part_u32 = h_u32 + 65536u;   // part: 4096 ull = 32 KB

    const int tid    = threadIdx.x;
    const int e_pair = tid & 3;        // owns e0 = 2*e_pair, e1 = 2*e_pair+1 (local)
    const int c4     = tid >> 2;       // 0..63: k-block id
    const int e0loc  = e_pair * 2;
    const int e0     = blockIdx.x * 8 + e0loc;

    const float alpha = __expf(la[0]);

    // Loop-invariant packed weights: w2[e][g*4+kk] = {w,w}, k = g*256 + c4*4 + kk
    ull w2[2][16];
#pragma unroll
    for (int g = 0; g < 4; g++)
#pragma unroll
        for (int kk = 0; kk < 4; kk++) {
            int k = g * 256 + c4 * 4 + kk;
            w2[0][g * 4 + kk] = pack2(Wh[(size_t)e0 * DIM + k]);
            w2[1][g * 4 + kk] = pack2(Wh[(size_t)(e0 + 1) * DIM + k]);
        }

    // Precomputed swizzled smem addresses for this thread's 16 (kk,q) slots
    // within its 256B block: sptr[S] = h + c4*256 + ((S + c4)&15)*16.
    uint32_t sptr[16];
#pragma unroll
    for (int S = 0; S < 16; S++)
        sptr[S] = h_u32 + (uint32_t)(c4 * 256) + (uint32_t)(((S + c4) & 15) << 4);

    // Finalize role (tid < 128): output element (b = fb, e = eg).
    const int fb = tid >> 3;
    const int fe = tid & 7;
    const int eg = blockIdx.x * 8 + fe;

    // Finalize h_old smem address (transposed + swizzled): k = eg, batch fb.
    uint32_t hold_addr;
    {
        int g  = eg >> 8, kin = eg & 255;
        int cb = kin >> 2, kkb = kin & 3;
        int qb = fb >> 2,  rb  = fb & 3;
        hold_addr = h_u32 + (uint32_t)(g * 16384 + cb * 256 +
                     (((kkb * 4 + qb + cb) & 15) << 4) + rb * 4);
    }
    const uint32_t pread = part_u32 + (uint32_t)((fb >> 1) * 64 + fe * 8 + (fb & 1) * 4);

    for (int t = 0; t < T_STEPS; t++) {
        const size_t obase = (size_t)t * STEP_ELEMS;
        const float* hsrc = g_hscr[t & 1];
        float*       hdst = g_hscr[(t + 1) & 1];

        float wx = 0.0f;
        if (tid < 128) wx = outs[obase + (size_t)fb * DIM + eg];

        // Issue 4 k-groups of cp.async (16 KB each), swizzled dst, coalesced src.
#pragma unroll
        for (int g = 0; g < 4; g++) {
#pragma unroll
            for (int i = 0; i < 4; i++) {
                int u = i * 256 + tid;          // 16B-unit index within group
                int blk = u >> 4, slot = u & 15;
                uint32_t dst = h_u32 + (uint32_t)(g * 16384 + blk * 256 +
                                (((slot + blk) & 15) << 4));
                cp_async16(dst, hsrc + g * 4096 + u * 4);
            }
            cp_commit();
        }

        ull acc[2][8];
#pragma unroll
        for (int e = 0; e < 2; e++)
#pragma unroll
            for (int bp = 0; bp < 8; bp++) acc[e][bp] = 0ull;

#define RNN_GROUP(G, WAITN)                                                     \
        do {                                                                    \
            CP_WAIT(WAITN);                                                     \
            __syncthreads();                                                    \
            _Pragma("unroll")                                                   \
            for (int kk = 0; kk < 4; kk++) {                                    \
                const ull wa = w2[0][(G) * 4 + kk];                             \
                const ull wb = w2[1][(G) * 4 + kk];                             \
                _Pragma("unroll")                                               \
                for (int q = 0; q < 4; q++) {                                   \
                    ull lo, hi;                                                 \
                    lds128(lo, hi, sptr[kk * 4 + q] + (uint32_t)((G) * 16384)); \
                    ffma2(acc[0][2 * q],     lo, wa);                           \
                    ffma2(acc[0][2 * q + 1], hi, wa);                           \
                    ffma2(acc[1][2 * q],     lo, wb);                           \
                    ffma2(acc[1][2 * q + 1], hi, wb);                           \
                }                                                               \
            }                                                                   \
        } while (0)

        RNN_GROUP(0, 3);
        RNN_GROUP(1, 2);
        RNN_GROUP(2, 1);
        RNN_GROUP(3, 0);
#undef RNN_GROUP

        // part[(c4*8 + bp)*8 + e] (ull = batches {2bp, 2bp+1} for column e)
#pragma unroll
        for (int bp = 0; bp < 8; bp++) {
            uint32_t pa = part_u32 + (uint32_t)((((c4 * 8 + bp) * 8) + e0loc) * 8);
            sts128(pa, acc[0][bp], acc[1][bp]);
        }
        __syncthreads();

        float ot = 0.0f;
        if (tid < 128) {
            float s0 = 0.f, s1 = 0.f, s2 = 0.f, s3 = 0.f;
#pragma unroll
            for (int c = 0; c < 64; c += 4) {
                s0 += lds32(pread + (uint32_t)((c + 0) * 512));
                s1 += lds32(pread + (uint32_t)((c + 1) * 512));
                s2 += lds32(pread + (uint32_t)((c + 2) * 512));
                s3 += lds32(pread + (uint32_t)((c + 3) * 512));
            }
            float pre  = (s0 + s1) + (s2 + s3) + wx;
            float hold = lds32(hold_addr);
            float hn   = hold + alpha * my_tanh(pre);
            ot         = hn * hn * my_sigmoid(hn);
            hbuf[(size_t)(t + 1) * STEP_ELEMS + (size_t)fb * DIM + eg] = hn;
            hdst[eg * 16 + fb] = hn;   // transposed scratch for next step
        }
        __syncthreads();   // all stores of this CTA issued

        if (tid == 0) bar_arrive_release();

        if (tid < 128) outs[obase + (size_t)fb * DIM + eg] = ot;

        if (tid == 0) {
            const unsigned tgt = (unsigned)(t + 1) * NCTA;
            while (bar_ld_acquire() < tgt) { }
        }
        __syncthreads();
    }
}

// ---------------------------------------------------------------------------
// kernel_launch
//   inputs: x[T,B,D], h0[B,D], W_x[D,D], W_h[D,D], b[D], log_alpha[1]
//   output: [ outs (T*B*D) | h ((T+1)*B*D) ] float32
//   outs doubles as Wx_all scratch; h broadcast goes through g_hscr ping-pong.
// ---------------------------------------------------------------------------
extern "C" void kernel_launch(void* const* d_in, const int* in_sizes, int n_in,
                              void* d_out, int out_size) {
    const float* x    = (const float*)d_in[0];
    const float* h0   = (const float*)d_in[1];
    const float* Wx   = (const float*)d_in[2];
    const float* Wh   = (const float*)d_in[3];
    const float* bias = (const float*)d_in[4];
    const float* la   = (const float*)d_in[5];

    float* outs = (float*)d_out;
    float* hbuf = outs + OUTS_ELEMS;

    cudaFuncSetAttribute(rnn_kernel, cudaFuncAttributeMaxDynamicSharedMemorySize,
                         65536 + 32768);

    init_kernel<<<32, 512>>>(h0, hbuf);

    dim3 gg(32768 / 128, DIM / 128);
    gemm_kernel<<<gg, 256>>>(x, Wx, bias, outs);

    rnn_kernel<<<NCTA, 256, 65536 + 32768>>>(Wh, la, outs, hbuf);
}